// round 3
// baseline (speedup 1.0000x reference)
#include <cuda_runtime.h>
#include <cuda_bf16.h>

// Problem: reference builds the full 8192x8192 pairwise-distance matrix and
// gathers 100 entries: out[k] = dist(X[ids[2k]], X[ids[2k+1]]), D=64.
// We compute only the 100 needed distances with tfa semantics:
//   d2 = ||xi||^2 + ||xj||^2 - 2*dot(xi,xj);  d = d2 > 0 ? sqrt(d2) : 0.
//
// Two pairs per warp: each 16-lane half-warp owns one pair. Lane l (within
// the half-warp) loads float4 at columns [4l..4l+3] of both rows (16 lanes x
// 16B = 256B per row, fully coalesced), accumulates si, sj, dot; 4-step
// butterfly reduce within the half-warp; half-lane 0 writes.

#define CARD 50
#define NPAIRS (2 * CARD)   // 100 output distances
#define DIMS 64

__global__ void rips_pairs_kernel(const float* __restrict__ X,
                                  const int* __restrict__ ids,
                                  float* __restrict__ out) {
    int tid  = blockIdx.x * blockDim.x + threadIdx.x;
    int pair = tid >> 4;          // one pair per 16 threads
    int hl   = tid & 15;          // lane within half-warp
    if (pair >= NPAIRS) return;

    // Both indices in one LDG.64.
    int2 ij = __ldg(reinterpret_cast<const int2*>(ids) + pair);

    const float4* rowi = reinterpret_cast<const float4*>(X + (long)ij.x * DIMS);
    const float4* rowj = reinterpret_cast<const float4*>(X + (long)ij.y * DIMS);

    // Issue both row loads before any math: MLP=2, DRAM latency paid once.
    float4 a = __ldg(&rowi[hl]);
    float4 b = __ldg(&rowj[hl]);

    float si  = a.x * a.x + a.y * a.y + a.z * a.z + a.w * a.w;
    float sj  = b.x * b.x + b.y * b.y + b.z * b.z + b.w * b.w;
    float dot = a.x * b.x + a.y * b.y + a.z * b.z + a.w * b.w;

    // Butterfly reduce within the 16-lane half-warp.
    #pragma unroll
    for (int off = 8; off > 0; off >>= 1) {
        si  += __shfl_xor_sync(0xFFFFFFFFu, si,  off);
        sj  += __shfl_xor_sync(0xFFFFFFFFu, sj,  off);
        dot += __shfl_xor_sync(0xFFFFFFFFu, dot, off);
    }

    if (hl == 0) {
        float d2 = si + sj - 2.0f * dot;
        out[pair] = (d2 > 0.0f) ? sqrtf(d2) : 0.0f;
    }
}

extern "C" void kernel_launch(void* const* d_in, const int* in_sizes, int n_in,
                              void* d_out, int out_size) {
    const float* X   = (const float*)d_in[0];   // [8192, 64] float32
    const int*   ids = (const int*)d_in[1];     // [200] int32
    float*       out = (float*)d_out;           // [50, 2] = 100 floats

    // 100 pairs * 16 threads = 1600 threads -> 7 blocks x 256
    rips_pairs_kernel<<<7, 256>>>(X, ids, out);
}